// round 6
// baseline (speedup 1.0000x reference)
#include <cuda_runtime.h>
#include <cuda_bf16.h>
#include <math.h>
#include <stdint.h>

// Problem constants
#define BB 32
#define CC 64
#define VV 1024
#define TT 24
#define COUT 64
#define MROWS (BB*CC)            // 2048
#define PART ((size_t)MROWS*VV)  // 2,097,152 floats
#define CVSZ (CC*VV)             // 65536

// ---------------------------------------------------------------------------
__device__ __forceinline__ uint32_t smem_to_u32(const void* p) {
    uint32_t a;
    asm("{ .reg .u64 t; cvta.to.shared.u64 t, %1; cvt.u32.u64 %0, t; }" : "=r"(a) : "l"(p));
    return a;
}
__device__ __forceinline__ uint32_t lds32(uint32_t a) {
    uint32_t v; asm("ld.shared.b32 %0, [%1];" : "=r"(v) : "r"(a)); return v;
}
__device__ __forceinline__ void cpasync16(uint32_t dst, const void* src) {
    asm volatile("cp.async.cg.shared.global [%0], [%1], 16;" :: "r"(dst), "l"(src));
}
#define CP_COMMIT() asm volatile("cp.async.commit_group;" ::: "memory")
#define CP_WAIT(n)  asm volatile("cp.async.wait_group %0;" :: "n"(n) : "memory")

__device__ __forceinline__ void ldsm_x4(uint32_t* r, uint32_t a) {
    asm volatile("ldmatrix.sync.aligned.m8n8.x4.shared.b16 {%0,%1,%2,%3}, [%4];"
                 : "=r"(r[0]), "=r"(r[1]), "=r"(r[2]), "=r"(r[3]) : "r"(a));
}
__device__ __forceinline__ void ldsm_x4_trans(uint32_t* r, uint32_t a) {
    asm volatile("ldmatrix.sync.aligned.m8n8.x4.trans.shared.b16 {%0,%1,%2,%3}, [%4];"
                 : "=r"(r[0]), "=r"(r[1]), "=r"(r[2]), "=r"(r[3]) : "r"(a));
}

// m16n8k16 row.col bf16 -> fp32 accumulate
__device__ __forceinline__ void mma16816(float* c, const uint32_t* a, const uint32_t* b) {
    asm volatile(
        "mma.sync.aligned.m16n8k16.row.col.f32.bf16.bf16.f32 "
        "{%0,%1,%2,%3}, {%4,%5,%6,%7}, {%8,%9}, {%0,%1,%2,%3};"
        : "+f"(c[0]), "+f"(c[1]), "+f"(c[2]), "+f"(c[3])
        : "r"(a[0]), "r"(a[1]), "r"(a[2]), "r"(a[3]), "r"(b[0]), "r"(b[1]));
}

__device__ __forceinline__ float sigf(float x) { return 1.0f / (1.0f + __expf(-x)); }
__device__ __forceinline__ float tanh_fast(float x) {
    float y; asm("tanh.approx.f32 %0, %1;" : "=f"(y) : "f"(x)); return y;
}
__device__ __forceinline__ uint32_t packbf2(float a, float b) {
    return ((uint32_t)__bfloat16_as_ushort(__float2bfloat16(b)) << 16) |
           (uint32_t)__bfloat16_as_ushort(__float2bfloat16(a));
}

// ---------------------------------------------------------------------------
// Scratch
__device__ __align__(128) float g_xT[(size_t)TT*MROWS*VV];
__device__ __align__(128) float g_ys[(size_t)TT*MROWS*VV];
__device__ __align__(128) float g_c[(size_t)MROWS*VV];
__device__ __align__(128) __nv_bfloat16 g_combhi[(size_t)MROWS*VV];
__device__ __align__(128) __nv_bfloat16 g_comblo[(size_t)MROWS*VV];
__device__ __align__(128) __nv_bfloat16 g_x1hi[(size_t)MROWS*VV];
__device__ __align__(128) __nv_bfloat16 g_x1lo[(size_t)MROWS*VV];
__device__ __align__(128) __nv_bfloat16 g_x2hi[(size_t)MROWS*VV];
__device__ __align__(128) __nv_bfloat16 g_x2lo[(size_t)MROWS*VV];
__device__ __align__(128) __nv_bfloat16 g_Bhi[(size_t)VV*VV];  // A^T hi [n][k]
__device__ __align__(128) __nv_bfloat16 g_Blo[(size_t)VV*VV];  // A^T lo [n][k]
__device__ __align__(128) __nv_bfloat16 g_Whi[256*192];        // permuted W hi [p][k]
__device__ __align__(128) __nv_bfloat16 g_Wlo[256*192];        // permuted W lo [p][k]

// ---------------------------------------------------------------------------
__global__ void transpose_x(const float* __restrict__ x) {
    __shared__ float tile[32][25];
    int r  = blockIdx.x;
    int v0 = blockIdx.y * 32;
    const float* src = x + ((size_t)r * VV + v0) * TT;
    for (int i = threadIdx.x; i < 32 * TT; i += blockDim.x) {
        int v = i / TT, t = i % TT;
        tile[v][t] = src[i];
    }
    __syncthreads();
    for (int i = threadIdx.x; i < 32 * TT; i += blockDim.x) {
        int t = i / 32, v = i % 32;
        g_xT[(size_t)t * PART + (size_t)r * VV + v0 + v] = tile[v][t];
    }
}

__global__ void zero_c() {
    size_t i = (size_t)blockIdx.x * blockDim.x + threadIdx.x;
    g_c[i] = 0.0f;
}

// Bhi/Blo[n][k] = bf16split(A[k][n])
__global__ void bsplit(const float* __restrict__ A) {
    __shared__ float tile[32][33];
    int k0 = blockIdx.x * 32, n0 = blockIdx.y * 32;
    int tx = threadIdx.x & 31, ty = threadIdx.x >> 5;
    #pragma unroll
    for (int i = 0; i < 4; i++) {
        int k = ty + i * 8;
        tile[k][tx] = A[(size_t)(k0 + k) * VV + n0 + tx];
    }
    __syncthreads();
    #pragma unroll
    for (int i = 0; i < 4; i++) {
        int n = ty + i * 8;
        float v = tile[tx][n];
        __nv_bfloat16 h = __float2bfloat16(v);
        __nv_bfloat16 l = __float2bfloat16(v - __bfloat162float(h));
        g_Bhi[(size_t)(n0 + n) * VV + k0 + tx] = h;
        g_Blo[(size_t)(n0 + n) * VV + k0 + tx] = l;
    }
}

// Permuted W split: p = wm*64 + g*16 + cl  <->  o = g*64 + wm*16 + cl
__global__ void wsplit(const float* __restrict__ W) {
    int p = blockIdx.x;
    int k = threadIdx.x;
    int wm = p >> 6, g = (p >> 4) & 3, cl = p & 15;
    int o = g * 64 + wm * 16 + cl;
    float v = W[(size_t)o * 192 + k];
    __nv_bfloat16 h = __float2bfloat16(v);
    __nv_bfloat16 l = __float2bfloat16(v - __bfloat162float(h));
    g_Whi[p * 192 + k] = h;
    g_Wlo[p * 192 + k] = l;
}

// comb init for t=0: comb = x0 (h = 0)
__global__ void comb_init(const float* __restrict__ xt) {
    size_t i = ((size_t)blockIdx.x * blockDim.x + threadIdx.x) * 4;
    float4 v = *reinterpret_cast<const float4*>(xt + i);
    float hx = __bfloat162float(__float2bfloat16(v.x));
    float hy = __bfloat162float(__float2bfloat16(v.y));
    float hz = __bfloat162float(__float2bfloat16(v.z));
    float hw = __bfloat162float(__float2bfloat16(v.w));
    *reinterpret_cast<uint2*>(g_combhi + i) =
        make_uint2(packbf2(v.x, v.y), packbf2(v.z, v.w));
    *reinterpret_cast<uint2*>(g_comblo + i) =
        make_uint2(packbf2(v.x - hx, v.y - hy), packbf2(v.z - hz, v.w - hw));
}

// ---------------------------------------------------------------------------
// Hop GEMM via mma.sync bf16 split-3. CTA tile 128(M) x 64(N), 256 CTAs,
// 2 CTAs/SM. Double-buffered cp.async, 80B row stride (conflict-free).
#define ROWB 80
#define APLANE (128*ROWB)            // 10240
#define BPLANE (64*ROWB)             // 5120
#define HBUF (2*APLANE + 2*BPLANE)   // 30720
#define HOP_SMEM (2*HBUF)            // 61440

__global__ __launch_bounds__(256, 2) void hop_mma(
    const __nv_bfloat16* __restrict__ Ahi, const __nv_bfloat16* __restrict__ Alo,
    __nv_bfloat16* __restrict__ Chi, __nv_bfloat16* __restrict__ Clo)
{
    extern __shared__ char smem[];
    uint32_t sb = smem_to_u32(smem);
    const int tid = threadIdx.x, lane = tid & 31, wid = tid >> 5;
    const int wm = wid & 3, wn = wid >> 2;          // warp tile: M32 x N32
    const int m0 = blockIdx.y * 128, n0 = blockIdx.x * 64;
    const int lr  = lane >> 2;
    const int lc4 = (lane & 3) * 4;

    float acc[2][4][4];
    #pragma unroll
    for (int mt = 0; mt < 2; mt++)
        #pragma unroll
        for (int nt = 0; nt < 4; nt++)
            #pragma unroll
            for (int q = 0; q < 4; q++) acc[mt][nt][q] = 0.f;

    const int gr = tid >> 2, gc = tid & 3;

    auto load_chunk = [&](int k0, uint32_t base) {
        #pragma unroll
        for (int it = 0; it < 2; it++) {
            int row = gr + it * 64;
            uint32_t doff = (uint32_t)(row * ROWB + gc * 16);
            size_t ga = (((size_t)(m0 + row)) << 10) + k0 + gc * 8;
            cpasync16(base + doff,          Ahi + ga);
            cpasync16(base + APLANE + doff, Alo + ga);
        }
        {
            uint32_t doff = (uint32_t)(gr * ROWB + gc * 16);
            size_t gb = (((size_t)(n0 + gr)) << 10) + k0 + gc * 8;
            cpasync16(base + 2 * APLANE + doff,          g_Bhi + gb);
            cpasync16(base + 2 * APLANE + BPLANE + doff, g_Blo + gb);
        }
        CP_COMMIT();
    };

    load_chunk(0, sb);

    for (int chunk = 0; chunk < 32; chunk++) {
        uint32_t base = sb + (chunk & 1) * HBUF;
        if (chunk + 1 < 32) {
            load_chunk((chunk + 1) * 32, sb + ((chunk + 1) & 1) * HBUF);
            CP_WAIT(1);
        } else {
            CP_WAIT(0);
        }
        __syncthreads();

        uint32_t aB = base + (uint32_t)(wm * 32) * ROWB;
        uint32_t bB = base + 2 * APLANE + (uint32_t)(wn * 32) * ROWB;
        #pragma unroll
        for (int ks = 0; ks < 2; ks++) {
            uint32_t koff = (uint32_t)(ks * 32 + lc4);
            uint32_t ah[2][4], al[2][4];
            #pragma unroll
            for (int mt = 0; mt < 2; mt++) {
                uint32_t r0 = aB + (uint32_t)((mt * 16 + lr) * ROWB) + koff;
                ah[mt][0] = lds32(r0);
                ah[mt][1] = lds32(r0 + 8 * ROWB);
                ah[mt][2] = lds32(r0 + 16);
                ah[mt][3] = lds32(r0 + 8 * ROWB + 16);
                al[mt][0] = lds32(r0 + APLANE);
                al[mt][1] = lds32(r0 + APLANE + 8 * ROWB);
                al[mt][2] = lds32(r0 + APLANE + 16);
                al[mt][3] = lds32(r0 + APLANE + 8 * ROWB + 16);
            }
            uint32_t bh[4][2], bl[4][2];
            #pragma unroll
            for (int nt = 0; nt < 4; nt++) {
                uint32_t r0 = bB + (uint32_t)((nt * 8 + lr) * ROWB) + koff;
                bh[nt][0] = lds32(r0);
                bh[nt][1] = lds32(r0 + 16);
                bl[nt][0] = lds32(r0 + BPLANE);
                bl[nt][1] = lds32(r0 + BPLANE + 16);
            }
            #pragma unroll
            for (int mt = 0; mt < 2; mt++)
                #pragma unroll
                for (int nt = 0; nt < 4; nt++) {
                    mma16816(acc[mt][nt], ah[mt], bh[nt]);
                    mma16816(acc[mt][nt], ah[mt], bl[nt]);
                    mma16816(acc[mt][nt], al[mt], bh[nt]);
                }
        }
        __syncthreads();
    }

    // Epilogue: bf16 hi/lo planes
    #pragma unroll
    for (int mt = 0; mt < 2; mt++) {
        int row = m0 + wm * 32 + mt * 16 + lr;
        #pragma unroll
        for (int nt = 0; nt < 4; nt++) {
            int col = n0 + wn * 32 + nt * 8 + (lane & 3) * 2;
            float v0 = acc[mt][nt][0], v1 = acc[mt][nt][1];
            float v2 = acc[mt][nt][2], v3 = acc[mt][nt][3];
            float h0 = __bfloat162float(__float2bfloat16(v0));
            float h1 = __bfloat162float(__float2bfloat16(v1));
            float h2 = __bfloat162float(__float2bfloat16(v2));
            float h3 = __bfloat162float(__float2bfloat16(v3));
            size_t o0 = (size_t)row * 1024 + col;
            size_t o1 = (size_t)(row + 8) * 1024 + col;
            *reinterpret_cast<uint32_t*>(Chi + o0) = packbf2(v0, v1);
            *reinterpret_cast<uint32_t*>(Chi + o1) = packbf2(v2, v3);
            *reinterpret_cast<uint32_t*>(Clo + o0) = packbf2(v0 - h0, v1 - h1);
            *reinterpret_cast<uint32_t*>(Clo + o1) = packbf2(v2 - h2, v3 - h3);
        }
    }
}

// ---------------------------------------------------------------------------
// Tensorized gate GEMM + fused LSTM + fused comb_{t+1} generation.
#define RKW 80
#define RKG 144
#define WS_PLANE (256*RKW)
#define GS_PLANE (32*RKG)
#define GATE_CHUNK (2*WS_PLANE + 2*GS_PLANE)
#define GATE_SMEM (2*GATE_CHUNK)

__global__ __launch_bounds__(256) void gate_lstm_mma(
    const float* __restrict__ bias, float* __restrict__ ysOut,
    const float* __restrict__ xnext)
{
    extern __shared__ char smem[];
    uint32_t sb = smem_to_u32(smem);
    const int tid = threadIdx.x, lane = tid & 31, wid = tid >> 5;
    const int wm = wid & 3, wn = wid >> 2;
    const int v0 = blockIdx.x * 64;
    const int b  = blockIdx.y;
    const int grp = lane >> 3, lr8 = lane & 7;

    const __nv_bfloat16* GHI[3] = {g_combhi, g_x1hi, g_x2hi};
    const __nv_bfloat16* GLO[3] = {g_comblo, g_x1lo, g_x2lo};

    float acc[4][4][4];
    #pragma unroll
    for (int mt = 0; mt < 4; mt++)
        #pragma unroll
        for (int nt = 0; nt < 4; nt++)
            #pragma unroll
            for (int q = 0; q < 4; q++) acc[mt][nt][q] = 0.f;

    auto load_chunk = [&](int ck, uint32_t base) {
        const __nv_bfloat16* wh = g_Whi + (size_t)tid * 192 + ck * 32;
        const __nv_bfloat16* wl = g_Wlo + (size_t)tid * 192 + ck * 32;
        uint32_t wd = base + (uint32_t)tid * RKW;
        #pragma unroll
        for (int q = 0; q < 4; q++) {
            cpasync16(wd + q * 16,            wh + q * 8);
            cpasync16(wd + WS_PLANE + q * 16, wl + q * 8);
        }
        int plane = ck >> 1, coff = (ck & 1) * 32;
        int kl = tid >> 3, i8 = tid & 7;
        size_t gsrc = (((size_t)(b * 64 + coff + kl)) << 10) + v0 + i8 * 8;
        uint32_t gd = base + 2 * WS_PLANE + (uint32_t)(kl * RKG + i8 * 16);
        cpasync16(gd,            GHI[plane] + gsrc);
        cpasync16(gd + GS_PLANE, GLO[plane] + gsrc);
        CP_COMMIT();
    };

    load_chunk(0, sb);

    for (int ck = 0; ck < 6; ck++) {
        uint32_t base = sb + (ck & 1) * GATE_CHUNK;
        if (ck + 1 < 6) {
            load_chunk(ck + 1, sb + ((ck + 1) & 1) * GATE_CHUNK);
            CP_WAIT(1);
        } else {
            CP_WAIT(0);
        }
        __syncthreads();

        #pragma unroll
        for (int ks = 0; ks < 2; ks++) {
            uint32_t ah[4][4], al[4][4];
            #pragma unroll
            for (int mt = 0; mt < 4; mt++) {
                uint32_t a = base +
                    (uint32_t)((wm * 64 + mt * 16 + (grp & 1) * 8 + lr8) * RKW) +
                    (uint32_t)(ks * 32 + (grp >> 1) * 16);
                ldsm_x4(ah[mt], a);
                ldsm_x4(al[mt], a + WS_PLANE);
            }
            uint32_t bh[4][2], bl[4][2];
            #pragma unroll
            for (int h = 0; h < 2; h++) {
                uint32_t a = base + 2 * WS_PLANE +
                    (uint32_t)((ks * 16 + (grp & 1) * 8 + lr8) * RKG) +
                    (uint32_t)(wn * 64 + h * 32 + (grp >> 1) * 16);
                uint32_t r[4];
                ldsm_x4_trans(r, a);
                bh[2 * h][0] = r[0]; bh[2 * h][1] = r[1];
                bh[2 * h + 1][0] = r[2]; bh[2 * h + 1][1] = r[3];
                ldsm_x4_trans(r, a + GS_PLANE);
                bl[2 * h][0] = r[0]; bl[2 * h][1] = r[1];
                bl[2 * h + 1][0] = r[2]; bl[2 * h + 1][1] = r[3];
            }
            #pragma unroll
            for (int mt = 0; mt < 4; mt++)
                #pragma unroll
                for (int nt = 0; nt < 4; nt++) {
                    mma16816(acc[mt][nt], ah[mt], bh[nt]);
                    mma16816(acc[mt][nt], ah[mt], bl[nt]);
                    mma16816(acc[mt][nt], al[mt], bh[nt]);
                }
        }
        __syncthreads();
    }

    // Fused LSTM epilogue (+ comb_{t+1} generation).
    const int r = lane >> 2;
    const int q2 = (lane & 3) * 2;
    #pragma unroll
    for (int s = 0; s < 2; s++) {
        int c = wm * 16 + r + 8 * s;
        float bi = bias[c];
        float bf = bias[64 + c];
        float bg = bias[128 + c];
        float bo = bias[192 + c];
        #pragma unroll
        for (int nt = 0; nt < 4; nt++) {
            int v = v0 + wn * 32 + nt * 8 + q2;
            size_t idx = (size_t)b * CVSZ + (size_t)c * VV + v;
            float2 cold = *reinterpret_cast<const float2*>(g_c + idx);
            float i0 = acc[0][nt][2 * s]     + bi;
            float i1 = acc[0][nt][2 * s + 1] + bi;
            float f0 = acc[1][nt][2 * s]     + bf;
            float f1 = acc[1][nt][2 * s + 1] + bf;
            float g0 = acc[2][nt][2 * s]     + bg;
            float g1 = acc[2][nt][2 * s + 1] + bg;
            float o0 = acc[3][nt][2 * s]     + bo;
            float o1 = acc[3][nt][2 * s + 1] + bo;
            float cy0 = sigf(f0) * cold.x + sigf(i0) * g0;
            float cy1 = sigf(f1) * cold.y + sigf(i1) * g1;
            float hy0 = sigf(o0) * tanh_fast(cy0);
            float hy1 = sigf(o1) * tanh_fast(cy1);
            *reinterpret_cast<float2*>(g_c + idx)   = make_float2(cy0, cy1);
            *reinterpret_cast<float2*>(ysOut + idx) = make_float2(hy0, hy1);
            if (xnext) {
                float2 xv = *reinterpret_cast<const float2*>(xnext + idx);
                float cb0 = xv.x + hy0, cb1 = xv.y + hy1;
                float hb0 = __bfloat162float(__float2bfloat16(cb0));
                float hb1 = __bfloat162float(__float2bfloat16(cb1));
                *reinterpret_cast<uint32_t*>(g_combhi + idx) = packbf2(cb0, cb1);
                *reinterpret_cast<uint32_t*>(g_comblo + idx) = packbf2(cb0 - hb0, cb1 - hb1);
            }
        }
    }
}

// ---------------------------------------------------------------------------
__global__ __launch_bounds__(256) void proj_out(const float* __restrict__ Wout,
                                                const float* __restrict__ bout,
                                                float* __restrict__ out) {
    __shared__ float sm[TT * CC * 8];
    int b  = blockIdx.y;
    int v0 = blockIdx.x * 8;
    for (int i = threadIdx.x; i < TT * CC * 8; i += 256) {
        int t = i / (CC * 8);
        int rem = i % (CC * 8);
        int c = rem >> 3, vv = rem & 7;
        sm[i] = g_ys[(size_t)t * PART + (size_t)b * CVSZ + (size_t)c * VV + v0 + vv];
    }
    __syncthreads();
    for (int p = threadIdx.x; p < COUT * 8; p += 256) {
        int o = p >> 3, vv = p & 7;
        float accp[TT];
        #pragma unroll
        for (int t = 0; t < TT; t++) accp[t] = 0.f;
        for (int c = 0; c < CC; c++) {
            float w = Wout[o * CC + c];
            #pragma unroll
            for (int t = 0; t < TT; t++) accp[t] += w * sm[t * (CC * 8) + c * 8 + vv];
        }
        float bo = bout[o];
        float* op = out + ((size_t)(b * COUT + o) * VV + v0 + vv) * TT;
        #pragma unroll
        for (int t = 0; t < TT; t++) op[t] = accp[t] + bo;
    }
}

// ---------------------------------------------------------------------------
extern "C" void kernel_launch(void* const* d_in, const int* in_sizes, int n_in,
                              void* d_out, int out_size) {
    const float* x      = (const float*)d_in[0];
    const float* Amat   = (const float*)d_in[1];
    const float* W_gout = (const float*)d_in[2];
    const float* b_gout = (const float*)d_in[3];
    const float* W_out  = (const float*)d_in[4];
    const float* b_out  = (const float*)d_in[5];
    float* out = (float*)d_out;

    float *xT, *ys;
    __nv_bfloat16 *chi, *clo, *x1hi, *x1lo, *x2hi, *x2lo;
    cudaGetSymbolAddress((void**)&xT, g_xT);
    cudaGetSymbolAddress((void**)&ys, g_ys);
    cudaGetSymbolAddress((void**)&chi,  g_combhi);
    cudaGetSymbolAddress((void**)&clo,  g_comblo);
    cudaGetSymbolAddress((void**)&x1hi, g_x1hi);
    cudaGetSymbolAddress((void**)&x1lo, g_x1lo);
    cudaGetSymbolAddress((void**)&x2hi, g_x2hi);
    cudaGetSymbolAddress((void**)&x2lo, g_x2lo);

    cudaFuncSetAttribute(hop_mma, cudaFuncAttributeMaxDynamicSharedMemorySize, HOP_SMEM);
    cudaFuncSetAttribute(gate_lstm_mma, cudaFuncAttributeMaxDynamicSharedMemorySize, GATE_SMEM);

    transpose_x<<<dim3(MROWS, VV / 32), 256>>>(x);
    zero_c<<<(MROWS * VV) / 256, 256>>>();
    bsplit<<<dim3(32, 32), 256>>>(Amat);
    wsplit<<<256, 192>>>(W_gout);
    comb_init<<<(MROWS * VV / 4) / 256, 256>>>(xT);   // comb_0 = x_0

    dim3 hopGrid(VV / 64, MROWS / 128);    // (16, 16) = 256 CTAs
    dim3 gateGrid(VV / 64, BB);            // (16, 32)

    for (int t = 0; t < TT; t++) {
        hop_mma<<<hopGrid, 256, HOP_SMEM>>>(chi, clo, x1hi, x1lo);    // x1 = comb @ A
        hop_mma<<<hopGrid, 256, HOP_SMEM>>>(x1hi, x1lo, x2hi, x2lo);  // x2 = x1 @ A
        const float* xnext = (t + 1 < TT) ? (xT + (size_t)(t + 1) * PART) : nullptr;
        gate_lstm_mma<<<gateGrid, 256, GATE_SMEM>>>(b_gout, ys + (size_t)t * PART, xnext);
    }

    proj_out<<<dim3(VV / 8, BB), 256>>>(W_out, b_out, out);
}

// round 7
// speedup vs baseline: 1.0238x; 1.0238x over previous
#include <cuda_runtime.h>
#include <cuda_bf16.h>
#include <math.h>
#include <stdint.h>

// Problem constants
#define BB 32
#define CC 64
#define VV 1024
#define TT 24
#define COUT 64
#define MROWS (BB*CC)            // 2048
#define PART ((size_t)MROWS*VV)  // 2,097,152 floats
#define CVSZ (CC*VV)             // 65536

// ---------------------------------------------------------------------------
__device__ __forceinline__ uint32_t smem_to_u32(const void* p) {
    uint32_t a;
    asm("{ .reg .u64 t; cvta.to.shared.u64 t, %1; cvt.u32.u64 %0, t; }" : "=r"(a) : "l"(p));
    return a;
}
__device__ __forceinline__ uint32_t lds32(uint32_t a) {
    uint32_t v; asm("ld.shared.b32 %0, [%1];" : "=r"(v) : "r"(a)); return v;
}
__device__ __forceinline__ void cpasync16(uint32_t dst, const void* src) {
    asm volatile("cp.async.cg.shared.global [%0], [%1], 16;" :: "r"(dst), "l"(src));
}
#define CP_COMMIT() asm volatile("cp.async.commit_group;" ::: "memory")
#define CP_WAIT(n)  asm volatile("cp.async.wait_group %0;" :: "n"(n) : "memory")

__device__ __forceinline__ void ldsm_x4(uint32_t* r, uint32_t a) {
    asm volatile("ldmatrix.sync.aligned.m8n8.x4.shared.b16 {%0,%1,%2,%3}, [%4];"
                 : "=r"(r[0]), "=r"(r[1]), "=r"(r[2]), "=r"(r[3]) : "r"(a));
}
__device__ __forceinline__ void ldsm_x4_trans(uint32_t* r, uint32_t a) {
    asm volatile("ldmatrix.sync.aligned.m8n8.x4.trans.shared.b16 {%0,%1,%2,%3}, [%4];"
                 : "=r"(r[0]), "=r"(r[1]), "=r"(r[2]), "=r"(r[3]) : "r"(a));
}

// m16n8k16 row.col bf16 -> fp32 accumulate
__device__ __forceinline__ void mma16816(float* c, const uint32_t* a, const uint32_t* b) {
    asm volatile(
        "mma.sync.aligned.m16n8k16.row.col.f32.bf16.bf16.f32 "
        "{%0,%1,%2,%3}, {%4,%5,%6,%7}, {%8,%9}, {%0,%1,%2,%3};"
        : "+f"(c[0]), "+f"(c[1]), "+f"(c[2]), "+f"(c[3])
        : "r"(a[0]), "r"(a[1]), "r"(a[2]), "r"(a[3]), "r"(b[0]), "r"(b[1]));
}

__device__ __forceinline__ float sigf(float x) { return 1.0f / (1.0f + __expf(-x)); }
__device__ __forceinline__ float tanh_fast(float x) {
    float y; asm("tanh.approx.f32 %0, %1;" : "=f"(y) : "f"(x)); return y;
}
__device__ __forceinline__ uint32_t packbf2(float a, float b) {
    return ((uint32_t)__bfloat16_as_ushort(__float2bfloat16(b)) << 16) |
           (uint32_t)__bfloat16_as_ushort(__float2bfloat16(a));
}

// ---------------------------------------------------------------------------
// Scratch
__device__ __align__(128) float g_xT[(size_t)TT*MROWS*VV];
__device__ __align__(128) float g_ys[(size_t)TT*MROWS*VV];
__device__ __align__(128) float g_c[(size_t)MROWS*VV];
__device__ __align__(128) __nv_bfloat16 g_combhi[(size_t)MROWS*VV];
__device__ __align__(128) __nv_bfloat16 g_comblo[(size_t)MROWS*VV];
__device__ __align__(128) __nv_bfloat16 g_x1hi[(size_t)MROWS*VV];
__device__ __align__(128) __nv_bfloat16 g_x1lo[(size_t)MROWS*VV];
__device__ __align__(128) __nv_bfloat16 g_x2hi[(size_t)MROWS*VV];
__device__ __align__(128) __nv_bfloat16 g_x2lo[(size_t)MROWS*VV];
__device__ __align__(128) __nv_bfloat16 g_Bhi[(size_t)VV*VV];  // A^T hi [n][k]
__device__ __align__(128) __nv_bfloat16 g_Blo[(size_t)VV*VV];  // A^T lo [n][k]
__device__ __align__(128) __nv_bfloat16 g_Whi[256*192];        // permuted W hi [p][k]
__device__ __align__(128) __nv_bfloat16 g_Wlo[256*192];        // permuted W lo [p][k]

// ---------------------------------------------------------------------------
__global__ void transpose_x(const float* __restrict__ x) {
    __shared__ float tile[32][25];
    int r  = blockIdx.x;
    int v0 = blockIdx.y * 32;
    const float* src = x + ((size_t)r * VV + v0) * TT;
    for (int i = threadIdx.x; i < 32 * TT; i += blockDim.x) {
        int v = i / TT, t = i % TT;
        tile[v][t] = src[i];
    }
    __syncthreads();
    for (int i = threadIdx.x; i < 32 * TT; i += blockDim.x) {
        int t = i / 32, v = i % 32;
        g_xT[(size_t)t * PART + (size_t)r * VV + v0 + v] = tile[v][t];
    }
}

__global__ void zero_c() {
    size_t i = (size_t)blockIdx.x * blockDim.x + threadIdx.x;
    g_c[i] = 0.0f;
}

// Bhi/Blo[n][k] = bf16split(A[k][n])
__global__ void bsplit(const float* __restrict__ A) {
    __shared__ float tile[32][33];
    int k0 = blockIdx.x * 32, n0 = blockIdx.y * 32;
    int tx = threadIdx.x & 31, ty = threadIdx.x >> 5;
    #pragma unroll
    for (int i = 0; i < 4; i++) {
        int k = ty + i * 8;
        tile[k][tx] = A[(size_t)(k0 + k) * VV + n0 + tx];
    }
    __syncthreads();
    #pragma unroll
    for (int i = 0; i < 4; i++) {
        int n = ty + i * 8;
        float v = tile[tx][n];
        __nv_bfloat16 h = __float2bfloat16(v);
        __nv_bfloat16 l = __float2bfloat16(v - __bfloat162float(h));
        g_Bhi[(size_t)(n0 + n) * VV + k0 + tx] = h;
        g_Blo[(size_t)(n0 + n) * VV + k0 + tx] = l;
    }
}

// Permuted W split: p = wm*64 + g*16 + cl  <->  o = g*64 + wm*16 + cl
__global__ void wsplit(const float* __restrict__ W) {
    int p = blockIdx.x;
    int k = threadIdx.x;
    int wm = p >> 6, g = (p >> 4) & 3, cl = p & 15;
    int o = g * 64 + wm * 16 + cl;
    float v = W[(size_t)o * 192 + k];
    __nv_bfloat16 h = __float2bfloat16(v);
    __nv_bfloat16 l = __float2bfloat16(v - __bfloat162float(h));
    g_Whi[p * 192 + k] = h;
    g_Wlo[p * 192 + k] = l;
}

// comb init for t=0: comb = x0 (h = 0)
__global__ void comb_init(const float* __restrict__ xt) {
    size_t i = ((size_t)blockIdx.x * blockDim.x + threadIdx.x) * 4;
    float4 v = *reinterpret_cast<const float4*>(xt + i);
    float hx = __bfloat162float(__float2bfloat16(v.x));
    float hy = __bfloat162float(__float2bfloat16(v.y));
    float hz = __bfloat162float(__float2bfloat16(v.z));
    float hw = __bfloat162float(__float2bfloat16(v.w));
    *reinterpret_cast<uint2*>(g_combhi + i) =
        make_uint2(packbf2(v.x, v.y), packbf2(v.z, v.w));
    *reinterpret_cast<uint2*>(g_comblo + i) =
        make_uint2(packbf2(v.x - hx, v.y - hy), packbf2(v.z - hz, v.w - hw));
}

// ---------------------------------------------------------------------------
// Hop GEMM via mma.sync bf16 split-3 (R5 winner: 128x128 tile, 128 CTAs).
#define ROWB 80
#define PLANE 10240                 // 128 rows * 80B
#define BUFB  (4*PLANE)
#define HOP_SMEM (2*BUFB)           // 81920

__global__ __launch_bounds__(256, 1) void hop_mma(
    const __nv_bfloat16* __restrict__ Ahi, const __nv_bfloat16* __restrict__ Alo,
    __nv_bfloat16* __restrict__ Chi, __nv_bfloat16* __restrict__ Clo)
{
    extern __shared__ char smem[];
    uint32_t sb = smem_to_u32(smem);
    const int tid = threadIdx.x, lane = tid & 31, wid = tid >> 5;
    const int wm = wid & 3, wn = wid >> 2;          // warp tile: M32 x N64
    const int m0 = blockIdx.y * 128, n0 = blockIdx.x * 128;
    const int lr  = lane >> 2;
    const int lc4 = (lane & 3) * 4;

    float acc[2][8][4];
    #pragma unroll
    for (int mt = 0; mt < 2; mt++)
        #pragma unroll
        for (int nt = 0; nt < 8; nt++)
            #pragma unroll
            for (int q = 0; q < 4; q++) acc[mt][nt][q] = 0.f;

    const int gr = tid >> 2, gc = tid & 3;

    {
        uint32_t base = sb;
        #pragma unroll
        for (int it = 0; it < 2; it++) {
            int row = gr + it * 64;
            uint32_t doff = (uint32_t)(row * ROWB + gc * 16);
            size_t ga = (((size_t)(m0 + row)) << 10) + gc * 8;
            size_t gb = (((size_t)(n0 + row)) << 10) + gc * 8;
            cpasync16(base + doff,             Ahi   + ga);
            cpasync16(base + PLANE + doff,     Alo   + ga);
            cpasync16(base + 2 * PLANE + doff, g_Bhi + gb);
            cpasync16(base + 3 * PLANE + doff, g_Blo + gb);
        }
        CP_COMMIT();
    }

    for (int chunk = 0; chunk < 32; chunk++) {
        uint32_t base = sb + (chunk & 1) * BUFB;
        if (chunk + 1 < 32) {
            uint32_t nbase = sb + ((chunk + 1) & 1) * BUFB;
            int k0 = (chunk + 1) * 32;
            #pragma unroll
            for (int it = 0; it < 2; it++) {
                int row = gr + it * 64;
                uint32_t doff = (uint32_t)(row * ROWB + gc * 16);
                size_t ga = (((size_t)(m0 + row)) << 10) + k0 + gc * 8;
                size_t gb = (((size_t)(n0 + row)) << 10) + k0 + gc * 8;
                cpasync16(nbase + doff,             Ahi   + ga);
                cpasync16(nbase + PLANE + doff,     Alo   + ga);
                cpasync16(nbase + 2 * PLANE + doff, g_Bhi + gb);
                cpasync16(nbase + 3 * PLANE + doff, g_Blo + gb);
            }
            CP_COMMIT();
            CP_WAIT(1);
        } else {
            CP_WAIT(0);
        }
        __syncthreads();

        uint32_t aB = base + (uint32_t)(wm * 32) * ROWB;
        uint32_t bB = base + 2 * PLANE + (uint32_t)(wn * 64) * ROWB;
        #pragma unroll
        for (int ks = 0; ks < 2; ks++) {
            uint32_t koff = (uint32_t)(ks * 32 + lc4);
            uint32_t ah[2][4], al[2][4];
            #pragma unroll
            for (int mt = 0; mt < 2; mt++) {
                uint32_t r0 = aB + (uint32_t)((mt * 16 + lr) * ROWB) + koff;
                ah[mt][0] = lds32(r0);
                ah[mt][1] = lds32(r0 + 8 * ROWB);
                ah[mt][2] = lds32(r0 + 16);
                ah[mt][3] = lds32(r0 + 8 * ROWB + 16);
                al[mt][0] = lds32(r0 + PLANE);
                al[mt][1] = lds32(r0 + PLANE + 8 * ROWB);
                al[mt][2] = lds32(r0 + PLANE + 16);
                al[mt][3] = lds32(r0 + PLANE + 8 * ROWB + 16);
            }
            uint32_t bh[8][2], bl[8][2];
            #pragma unroll
            for (int nt = 0; nt < 8; nt++) {
                uint32_t r0 = bB + (uint32_t)((nt * 8 + lr) * ROWB) + koff;
                bh[nt][0] = lds32(r0);
                bh[nt][1] = lds32(r0 + 16);
                bl[nt][0] = lds32(r0 + PLANE);
                bl[nt][1] = lds32(r0 + PLANE + 16);
            }
            #pragma unroll
            for (int mt = 0; mt < 2; mt++)
                #pragma unroll
                for (int nt = 0; nt < 8; nt++) {
                    mma16816(acc[mt][nt], ah[mt], bh[nt]);
                    mma16816(acc[mt][nt], ah[mt], bl[nt]);
                    mma16816(acc[mt][nt], al[mt], bh[nt]);
                }
        }
        __syncthreads();
    }

    // Epilogue: bf16 hi/lo planes
    #pragma unroll
    for (int mt = 0; mt < 2; mt++) {
        int row = m0 + wm * 32 + mt * 16 + lr;
        #pragma unroll
        for (int nt = 0; nt < 8; nt++) {
            int col = n0 + wn * 64 + nt * 8 + (lane & 3) * 2;
            float v0 = acc[mt][nt][0], v1 = acc[mt][nt][1];
            float v2 = acc[mt][nt][2], v3 = acc[mt][nt][3];
            float h0 = __bfloat162float(__float2bfloat16(v0));
            float h1 = __bfloat162float(__float2bfloat16(v1));
            float h2 = __bfloat162float(__float2bfloat16(v2));
            float h3 = __bfloat162float(__float2bfloat16(v3));
            size_t o0 = (size_t)row * 1024 + col;
            size_t o1 = (size_t)(row + 8) * 1024 + col;
            *reinterpret_cast<uint32_t*>(Chi + o0) = packbf2(v0, v1);
            *reinterpret_cast<uint32_t*>(Chi + o1) = packbf2(v2, v3);
            *reinterpret_cast<uint32_t*>(Clo + o0) = packbf2(v0 - h0, v1 - h1);
            *reinterpret_cast<uint32_t*>(Clo + o1) = packbf2(v2 - h2, v3 - h3);
        }
    }
}

// ---------------------------------------------------------------------------
// Tensorized gate GEMM + fused LSTM + fused comb_{t+1} generation.
// v-tile widened to 128: grid (8, 32) = 256 CTAs (1.73 waves vs 3.46).
// Warp tile M64 x N64: wm = wid&3, wn = wid>>2 (0..1).
#define RKW 80
#define RKG 272                                  // 128 cols * 2B + 16 pad
#define WS_PLANE (256*RKW)                       // 20480
#define GS_PLANE (32*RKG)                        // 8704
#define GATE_CHUNK (2*WS_PLANE + 2*GS_PLANE)     // 58368
#define GATE_SMEM (2*GATE_CHUNK)                 // 116736

__global__ __launch_bounds__(256, 1) void gate_lstm_mma(
    const float* __restrict__ bias, float* __restrict__ ysOut,
    const float* __restrict__ xnext)
{
    extern __shared__ char smem[];
    uint32_t sb = smem_to_u32(smem);
    const int tid = threadIdx.x, lane = tid & 31, wid = tid >> 5;
    const int wm = wid & 3, wn = wid >> 2;       // M64 x N64 warp tile
    const int v0 = blockIdx.x * 128;
    const int b  = blockIdx.y;
    const int grp = lane >> 3, lr8 = lane & 7;

    const __nv_bfloat16* GHI[3] = {g_combhi, g_x1hi, g_x2hi};
    const __nv_bfloat16* GLO[3] = {g_comblo, g_x1lo, g_x2lo};

    float acc[4][8][4];
    #pragma unroll
    for (int mt = 0; mt < 4; mt++)
        #pragma unroll
        for (int nt = 0; nt < 8; nt++)
            #pragma unroll
            for (int q = 0; q < 4; q++) acc[mt][nt][q] = 0.f;

    auto load_chunk = [&](int ck, uint32_t base) {
        // W planes: thread tid = row p, 4 x 16B per plane
        const __nv_bfloat16* wh = g_Whi + (size_t)tid * 192 + ck * 32;
        const __nv_bfloat16* wl = g_Wlo + (size_t)tid * 192 + ck * 32;
        uint32_t wd = base + (uint32_t)tid * RKW;
        #pragma unroll
        for (int q = 0; q < 4; q++) {
            cpasync16(wd + q * 16,            wh + q * 8);
            cpasync16(wd + WS_PLANE + q * 16, wl + q * 8);
        }
        // G planes: 32 rows x 256B; 8 threads/row, 2x16B each, both planes
        int plane = ck >> 1, coff = (ck & 1) * 32;
        int kl = tid >> 3, i8 = tid & 7;
        size_t gsrc = (((size_t)(b * 64 + coff + kl)) << 10) + v0 + i8 * 16;
        uint32_t gd = base + 2 * WS_PLANE + (uint32_t)(kl * RKG + i8 * 32);
        cpasync16(gd,                 GHI[plane] + gsrc);
        cpasync16(gd + 16,            GHI[plane] + gsrc + 8);
        cpasync16(gd + GS_PLANE,      GLO[plane] + gsrc);
        cpasync16(gd + GS_PLANE + 16, GLO[plane] + gsrc + 8);
        CP_COMMIT();
    };

    load_chunk(0, sb);

    for (int ck = 0; ck < 6; ck++) {
        uint32_t base = sb + (ck & 1) * GATE_CHUNK;
        if (ck + 1 < 6) {
            load_chunk(ck + 1, sb + ((ck + 1) & 1) * GATE_CHUNK);
            CP_WAIT(1);
        } else {
            CP_WAIT(0);
        }
        __syncthreads();

        #pragma unroll
        for (int ks = 0; ks < 2; ks++) {
            uint32_t ah[4][4], al[4][4];
            #pragma unroll
            for (int mt = 0; mt < 4; mt++) {
                uint32_t a = base +
                    (uint32_t)((wm * 64 + mt * 16 + (grp & 1) * 8 + lr8) * RKW) +
                    (uint32_t)(ks * 32 + (grp >> 1) * 16);
                ldsm_x4(ah[mt], a);
                ldsm_x4(al[mt], a + WS_PLANE);
            }
            uint32_t bh[8][2], bl[8][2];
            #pragma unroll
            for (int h = 0; h < 4; h++) {
                uint32_t a = base + 2 * WS_PLANE +
                    (uint32_t)((ks * 16 + (grp & 1) * 8 + lr8) * RKG) +
                    (uint32_t)(wn * 128 + h * 32 + (grp >> 1) * 16);
                uint32_t r[4];
                ldsm_x4_trans(r, a);
                bh[2 * h][0] = r[0]; bh[2 * h][1] = r[1];
                bh[2 * h + 1][0] = r[2]; bh[2 * h + 1][1] = r[3];
                ldsm_x4_trans(r, a + GS_PLANE);
                bl[2 * h][0] = r[0]; bl[2 * h][1] = r[1];
                bl[2 * h + 1][0] = r[2]; bl[2 * h + 1][1] = r[3];
            }
            #pragma unroll
            for (int mt = 0; mt < 4; mt++)
                #pragma unroll
                for (int nt = 0; nt < 8; nt++) {
                    mma16816(acc[mt][nt], ah[mt], bh[nt]);
                    mma16816(acc[mt][nt], ah[mt], bl[nt]);
                    mma16816(acc[mt][nt], al[mt], bh[nt]);
                }
        }
        __syncthreads();
    }

    // Fused LSTM epilogue + comb_{t+1} generation.
    const int r = lane >> 2;
    const int q2 = (lane & 3) * 2;
    #pragma unroll
    for (int s = 0; s < 2; s++) {
        int c = wm * 16 + r + 8 * s;
        float bi = bias[c];
        float bf = bias[64 + c];
        float bg = bias[128 + c];
        float bo = bias[192 + c];
        #pragma unroll
        for (int nt = 0; nt < 8; nt++) {
            int v = v0 + wn * 64 + nt * 8 + q2;
            size_t idx = (size_t)b * CVSZ + (size_t)c * VV + v;
            float2 cold = *reinterpret_cast<const float2*>(g_c + idx);
            float i0 = acc[0][nt][2 * s]     + bi;
            float i1 = acc[0][nt][2 * s + 1] + bi;
            float f0 = acc[1][nt][2 * s]     + bf;
            float f1 = acc[1][nt][2 * s + 1] + bf;
            float g0 = acc[2][nt][2 * s]     + bg;
            float g1 = acc[2][nt][2 * s + 1] + bg;
            float o0 = acc[3][nt][2 * s]     + bo;
            float o1 = acc[3][nt][2 * s + 1] + bo;
            float cy0 = sigf(f0) * cold.x + sigf(i0) * g0;
            float cy1 = sigf(f1) * cold.y + sigf(i1) * g1;
            float hy0 = sigf(o0) * tanh_fast(cy0);
            float hy1 = sigf(o1) * tanh_fast(cy1);
            *reinterpret_cast<float2*>(g_c + idx)   = make_float2(cy0, cy1);
            *reinterpret_cast<float2*>(ysOut + idx) = make_float2(hy0, hy1);
            if (xnext) {
                float2 xv = *reinterpret_cast<const float2*>(xnext + idx);
                float cb0 = xv.x + hy0, cb1 = xv.y + hy1;
                float hb0 = __bfloat162float(__float2bfloat16(cb0));
                float hb1 = __bfloat162float(__float2bfloat16(cb1));
                *reinterpret_cast<uint32_t*>(g_combhi + idx) = packbf2(cb0, cb1);
                *reinterpret_cast<uint32_t*>(g_comblo + idx) = packbf2(cb0 - hb0, cb1 - hb1);
            }
        }
    }
}

// ---------------------------------------------------------------------------
__global__ __launch_bounds__(256) void proj_out(const float* __restrict__ Wout,
                                                const float* __restrict__ bout,
                                                float* __restrict__ out) {
    __shared__ float sm[TT * CC * 8];
    int b  = blockIdx.y;
    int v0 = blockIdx.x * 8;
    for (int i = threadIdx.x; i < TT * CC * 8; i += 256) {
        int t = i / (CC * 8);
        int rem = i % (CC * 8);
        int c = rem >> 3, vv = rem & 7;
        sm[i] = g_ys[(size_t)t * PART + (size_t)b * CVSZ + (size_t)c * VV + v0 + vv];
    }
    __syncthreads();
    for (int p = threadIdx.x; p < COUT * 8; p += 256) {
        int o = p >> 3, vv = p & 7;
        float accp[TT];
        #pragma unroll
        for (int t = 0; t < TT; t++) accp[t] = 0.f;
        for (int c = 0; c < CC; c++) {
            float w = Wout[o * CC + c];
            #pragma unroll
            for (int t = 0; t < TT; t++) accp[t] += w * sm[t * (CC * 8) + c * 8 + vv];
        }
        float bo = bout[o];
        float* op = out + ((size_t)(b * COUT + o) * VV + v0 + vv) * TT;
        #pragma unroll
        for (int t = 0; t < TT; t++) op[t] = accp[t] + bo;
    }
}

// ---------------------------------------------------------------------------
extern "C" void kernel_launch(void* const* d_in, const int* in_sizes, int n_in,
                              void* d_out, int out_size) {
    const float* x      = (const float*)d_in[0];
    const float* Amat   = (const float*)d_in[1];
    const float* W_gout = (const float*)d_in[2];
    const float* b_gout = (const float*)d_in[3];
    const float* W_out  = (const float*)d_in[4];
    const float* b_out  = (const float*)d_in[5];
    float* out = (float*)d_out;

    float *xT, *ys;
    __nv_bfloat16 *chi, *clo, *x1hi, *x1lo, *x2hi, *x2lo;
    cudaGetSymbolAddress((void**)&xT, g_xT);
    cudaGetSymbolAddress((void**)&ys, g_ys);
    cudaGetSymbolAddress((void**)&chi,  g_combhi);
    cudaGetSymbolAddress((void**)&clo,  g_comblo);
    cudaGetSymbolAddress((void**)&x1hi, g_x1hi);
    cudaGetSymbolAddress((void**)&x1lo, g_x1lo);
    cudaGetSymbolAddress((void**)&x2hi, g_x2hi);
    cudaGetSymbolAddress((void**)&x2lo, g_x2lo);

    cudaFuncSetAttribute(hop_mma, cudaFuncAttributeMaxDynamicSharedMemorySize, HOP_SMEM);
    cudaFuncSetAttribute(gate_lstm_mma, cudaFuncAttributeMaxDynamicSharedMemorySize, GATE_SMEM);

    transpose_x<<<dim3(MROWS, VV / 32), 256>>>(x);
    zero_c<<<(MROWS * VV) / 256, 256>>>();
    bsplit<<<dim3(32, 32), 256>>>(Amat);
    wsplit<<<256, 192>>>(W_gout);
    comb_init<<<(MROWS * VV / 4) / 256, 256>>>(xT);   // comb_0 = x_0

    dim3 hopGrid(VV / 128, MROWS / 128);    // (8, 16) = 128 CTAs
    dim3 gateGrid(VV / 128, BB);            // (8, 32) = 256 CTAs

    for (int t = 0; t < TT; t++) {
        hop_mma<<<hopGrid, 256, HOP_SMEM>>>(chi, clo, x1hi, x1lo);    // x1 = comb @ A
        hop_mma<<<hopGrid, 256, HOP_SMEM>>>(x1hi, x1lo, x2hi, x2lo);  // x2 = x1 @ A
        const float* xnext = (t + 1 < TT) ? (xT + (size_t)(t + 1) * PART) : nullptr;
        gate_lstm_mma<<<gateGrid, 256, GATE_SMEM>>>(b_gout, ys + (size_t)t * PART, xnext);
    }

    proj_out<<<dim3(VV / 8, BB), 256>>>(W_out, b_out, out);
}

// round 8
// speedup vs baseline: 1.1710x; 1.1438x over previous
#include <cuda_runtime.h>
#include <cuda_bf16.h>
#include <math.h>
#include <stdint.h>

// Problem constants
#define BB 32
#define CC 64
#define VV 1024
#define TT 24
#define COUT 64
#define MROWS (BB*CC)            // 2048
#define PART ((size_t)MROWS*VV)  // 2,097,152 floats
#define CVSZ (CC*VV)             // 65536

// ---------------------------------------------------------------------------
__device__ __forceinline__ uint32_t smem_to_u32(const void* p) {
    uint32_t a;
    asm("{ .reg .u64 t; cvta.to.shared.u64 t, %1; cvt.u32.u64 %0, t; }" : "=r"(a) : "l"(p));
    return a;
}
__device__ __forceinline__ uint32_t lds32(uint32_t a) {
    uint32_t v; asm("ld.shared.b32 %0, [%1];" : "=r"(v) : "r"(a)); return v;
}
__device__ __forceinline__ void cpasync16(uint32_t dst, const void* src) {
    asm volatile("cp.async.cg.shared.global [%0], [%1], 16;" :: "r"(dst), "l"(src));
}
#define CP_COMMIT() asm volatile("cp.async.commit_group;" ::: "memory")
#define CP_WAIT(n)  asm volatile("cp.async.wait_group %0;" :: "n"(n) : "memory")

__device__ __forceinline__ void ldsm_x4_trans(uint32_t* r, uint32_t a) {
    asm volatile("ldmatrix.sync.aligned.m8n8.x4.trans.shared.b16 {%0,%1,%2,%3}, [%4];"
                 : "=r"(r[0]), "=r"(r[1]), "=r"(r[2]), "=r"(r[3]) : "r"(a));
}

// m16n8k16 row.col bf16 -> fp32 accumulate
__device__ __forceinline__ void mma16816(float* c, const uint32_t* a, const uint32_t* b) {
    asm volatile(
        "mma.sync.aligned.m16n8k16.row.col.f32.bf16.bf16.f32 "
        "{%0,%1,%2,%3}, {%4,%5,%6,%7}, {%8,%9}, {%0,%1,%2,%3};"
        : "+f"(c[0]), "+f"(c[1]), "+f"(c[2]), "+f"(c[3])
        : "r"(a[0]), "r"(a[1]), "r"(a[2]), "r"(a[3]), "r"(b[0]), "r"(b[1]));
}

__device__ __forceinline__ float sigf(float x) { return 1.0f / (1.0f + __expf(-x)); }
__device__ __forceinline__ float tanh_fast(float x) {
    float y; asm("tanh.approx.f32 %0, %1;" : "=f"(y) : "f"(x)); return y;
}
__device__ __forceinline__ uint32_t packbf2(float a, float b) {
    return ((uint32_t)__bfloat16_as_ushort(__float2bfloat16(b)) << 16) |
           (uint32_t)__bfloat16_as_ushort(__float2bfloat16(a));
}

// ---------------------------------------------------------------------------
// Scratch
__device__ __align__(128) float g_xT[(size_t)TT*MROWS*VV];
__device__ __align__(128) float g_ys[(size_t)TT*MROWS*VV];
__device__ __align__(128) float g_c[(size_t)MROWS*VV];
__device__ __align__(128) __nv_bfloat16 g_combhi[(size_t)MROWS*VV];
__device__ __align__(128) __nv_bfloat16 g_comblo[(size_t)MROWS*VV];
__device__ __align__(128) __nv_bfloat16 g_x1hi[(size_t)MROWS*VV];
__device__ __align__(128) __nv_bfloat16 g_x1lo[(size_t)MROWS*VV];
__device__ __align__(128) __nv_bfloat16 g_x2hi[(size_t)MROWS*VV];
__device__ __align__(128) __nv_bfloat16 g_x2lo[(size_t)MROWS*VV];
__device__ __align__(128) __nv_bfloat16 g_Bhi[(size_t)VV*VV];  // A^T hi [n][k]
__device__ __align__(128) __nv_bfloat16 g_Blo[(size_t)VV*VV];  // A^T lo [n][k]
// W as prepacked per-lane mma A-fragments: [tileM(16) x tileK(12) x lane(32)]
__device__ __align__(128) uint4 g_WfHi[16*12*32];
__device__ __align__(128) uint4 g_WfLo[16*12*32];

// ---------------------------------------------------------------------------
__global__ void transpose_x(const float* __restrict__ x) {
    __shared__ float tile[32][25];
    int r  = blockIdx.x;
    int v0 = blockIdx.y * 32;
    const float* src = x + ((size_t)r * VV + v0) * TT;
    for (int i = threadIdx.x; i < 32 * TT; i += blockDim.x) {
        int v = i / TT, t = i % TT;
        tile[v][t] = src[i];
    }
    __syncthreads();
    for (int i = threadIdx.x; i < 32 * TT; i += blockDim.x) {
        int t = i / 32, v = i % 32;
        g_xT[(size_t)t * PART + (size_t)r * VV + v0 + v] = tile[v][t];
    }
}

__global__ void zero_c() {
    size_t i = (size_t)blockIdx.x * blockDim.x + threadIdx.x;
    g_c[i] = 0.0f;
}

// Bhi/Blo[n][k] = bf16split(A[k][n])
__global__ void bsplit(const float* __restrict__ A) {
    __shared__ float tile[32][33];
    int k0 = blockIdx.x * 32, n0 = blockIdx.y * 32;
    int tx = threadIdx.x & 31, ty = threadIdx.x >> 5;
    #pragma unroll
    for (int i = 0; i < 4; i++) {
        int k = ty + i * 8;
        tile[k][tx] = A[(size_t)(k0 + k) * VV + n0 + tx];
    }
    __syncthreads();
    #pragma unroll
    for (int i = 0; i < 4; i++) {
        int n = ty + i * 8;
        float v = tile[tx][n];
        __nv_bfloat16 h = __float2bfloat16(v);
        __nv_bfloat16 l = __float2bfloat16(v - __bfloat162float(h));
        g_Bhi[(size_t)(n0 + n) * VV + k0 + tx] = h;
        g_Blo[(size_t)(n0 + n) * VV + k0 + tx] = l;
    }
}

// Prepack W into per-lane mma.m16n8k16 A-fragments (hi/lo planes).
// Permuted row p = wm*64 + g*16 + cl  <->  original o = g*64 + wm*16 + cl.
__global__ void wfrag(const float* __restrict__ W) {
    int tile = blockIdx.x;          // 0..191 = tileM*12 + tileK
    int lane = threadIdx.x;         // 0..31
    int tileM = tile / 12, tileK = tile % 12;
    int r = lane >> 2, c2 = (lane & 3) * 2;

    auto getw = [&](int pr, int k) -> float {
        int wm = pr >> 6, g = (pr >> 4) & 3, cl = pr & 15;
        int o = g * 64 + wm * 16 + cl;
        return W[(size_t)o * 192 + k];
    };
    int p0 = tileM * 16 + r, k0 = tileK * 16 + c2;
    float w[4][2];
    w[0][0] = getw(p0,     k0);     w[0][1] = getw(p0,     k0 + 1);
    w[1][0] = getw(p0 + 8, k0);     w[1][1] = getw(p0 + 8, k0 + 1);
    w[2][0] = getw(p0,     k0 + 8); w[2][1] = getw(p0,     k0 + 9);
    w[3][0] = getw(p0 + 8, k0 + 8); w[3][1] = getw(p0 + 8, k0 + 9);

    uint32_t hi[4], lo[4];
    #pragma unroll
    for (int q = 0; q < 4; q++) {
        float h0 = __bfloat162float(__float2bfloat16(w[q][0]));
        float h1 = __bfloat162float(__float2bfloat16(w[q][1]));
        hi[q] = packbf2(w[q][0], w[q][1]);
        lo[q] = packbf2(w[q][0] - h0, w[q][1] - h1);
    }
    g_WfHi[tile * 32 + lane] = make_uint4(hi[0], hi[1], hi[2], hi[3]);
    g_WfLo[tile * 32 + lane] = make_uint4(lo[0], lo[1], lo[2], lo[3]);
}

// comb init for t=0: comb = x0 (h = 0)
__global__ void comb_init(const float* __restrict__ xt) {
    size_t i = ((size_t)blockIdx.x * blockDim.x + threadIdx.x) * 4;
    float4 v = *reinterpret_cast<const float4*>(xt + i);
    float hx = __bfloat162float(__float2bfloat16(v.x));
    float hy = __bfloat162float(__float2bfloat16(v.y));
    float hz = __bfloat162float(__float2bfloat16(v.z));
    float hw = __bfloat162float(__float2bfloat16(v.w));
    *reinterpret_cast<uint2*>(g_combhi + i) =
        make_uint2(packbf2(v.x, v.y), packbf2(v.z, v.w));
    *reinterpret_cast<uint2*>(g_comblo + i) =
        make_uint2(packbf2(v.x - hx, v.y - hy), packbf2(v.z - hz, v.w - hw));
}

// ---------------------------------------------------------------------------
// Hop GEMM via mma.sync bf16 split-3 (R5 winner: 128x128 tile, 128 CTAs).
#define ROWB 80
#define PLANE 10240                 // 128 rows * 80B
#define BUFB  (4*PLANE)
#define HOP_SMEM (2*BUFB)           // 81920

__global__ __launch_bounds__(256, 1) void hop_mma(
    const __nv_bfloat16* __restrict__ Ahi, const __nv_bfloat16* __restrict__ Alo,
    __nv_bfloat16* __restrict__ Chi, __nv_bfloat16* __restrict__ Clo)
{
    extern __shared__ char smem[];
    uint32_t sb = smem_to_u32(smem);
    const int tid = threadIdx.x, lane = tid & 31, wid = tid >> 5;
    const int wm = wid & 3, wn = wid >> 2;          // warp tile: M32 x N64
    const int m0 = blockIdx.y * 128, n0 = blockIdx.x * 128;
    const int lr  = lane >> 2;
    const int lc4 = (lane & 3) * 4;

    float acc[2][8][4];
    #pragma unroll
    for (int mt = 0; mt < 2; mt++)
        #pragma unroll
        for (int nt = 0; nt < 8; nt++)
            #pragma unroll
            for (int q = 0; q < 4; q++) acc[mt][nt][q] = 0.f;

    const int gr = tid >> 2, gc = tid & 3;

    {
        uint32_t base = sb;
        #pragma unroll
        for (int it = 0; it < 2; it++) {
            int row = gr + it * 64;
            uint32_t doff = (uint32_t)(row * ROWB + gc * 16);
            size_t ga = (((size_t)(m0 + row)) << 10) + gc * 8;
            size_t gb = (((size_t)(n0 + row)) << 10) + gc * 8;
            cpasync16(base + doff,             Ahi   + ga);
            cpasync16(base + PLANE + doff,     Alo   + ga);
            cpasync16(base + 2 * PLANE + doff, g_Bhi + gb);
            cpasync16(base + 3 * PLANE + doff, g_Blo + gb);
        }
        CP_COMMIT();
    }

    for (int chunk = 0; chunk < 32; chunk++) {
        uint32_t base = sb + (chunk & 1) * BUFB;
        if (chunk + 1 < 32) {
            uint32_t nbase = sb + ((chunk + 1) & 1) * BUFB;
            int k0 = (chunk + 1) * 32;
            #pragma unroll
            for (int it = 0; it < 2; it++) {
                int row = gr + it * 64;
                uint32_t doff = (uint32_t)(row * ROWB + gc * 16);
                size_t ga = (((size_t)(m0 + row)) << 10) + k0 + gc * 8;
                size_t gb = (((size_t)(n0 + row)) << 10) + k0 + gc * 8;
                cpasync16(nbase + doff,             Ahi   + ga);
                cpasync16(nbase + PLANE + doff,     Alo   + ga);
                cpasync16(nbase + 2 * PLANE + doff, g_Bhi + gb);
                cpasync16(nbase + 3 * PLANE + doff, g_Blo + gb);
            }
            CP_COMMIT();
            CP_WAIT(1);
        } else {
            CP_WAIT(0);
        }
        __syncthreads();

        uint32_t aB = base + (uint32_t)(wm * 32) * ROWB;
        uint32_t bB = base + 2 * PLANE + (uint32_t)(wn * 64) * ROWB;
        #pragma unroll
        for (int ks = 0; ks < 2; ks++) {
            uint32_t koff = (uint32_t)(ks * 32 + lc4);
            uint32_t ah[2][4], al[2][4];
            #pragma unroll
            for (int mt = 0; mt < 2; mt++) {
                uint32_t r0 = aB + (uint32_t)((mt * 16 + lr) * ROWB) + koff;
                ah[mt][0] = lds32(r0);
                ah[mt][1] = lds32(r0 + 8 * ROWB);
                ah[mt][2] = lds32(r0 + 16);
                ah[mt][3] = lds32(r0 + 8 * ROWB + 16);
                al[mt][0] = lds32(r0 + PLANE);
                al[mt][1] = lds32(r0 + PLANE + 8 * ROWB);
                al[mt][2] = lds32(r0 + PLANE + 16);
                al[mt][3] = lds32(r0 + PLANE + 8 * ROWB + 16);
            }
            uint32_t bh[8][2], bl[8][2];
            #pragma unroll
            for (int nt = 0; nt < 8; nt++) {
                uint32_t r0 = bB + (uint32_t)((nt * 8 + lr) * ROWB) + koff;
                bh[nt][0] = lds32(r0);
                bh[nt][1] = lds32(r0 + 16);
                bl[nt][0] = lds32(r0 + PLANE);
                bl[nt][1] = lds32(r0 + PLANE + 16);
            }
            #pragma unroll
            for (int mt = 0; mt < 2; mt++)
                #pragma unroll
                for (int nt = 0; nt < 8; nt++) {
                    mma16816(acc[mt][nt], ah[mt], bh[nt]);
                    mma16816(acc[mt][nt], ah[mt], bl[nt]);
                    mma16816(acc[mt][nt], al[mt], bh[nt]);
                }
        }
        __syncthreads();
    }

    // Epilogue: bf16 hi/lo planes
    #pragma unroll
    for (int mt = 0; mt < 2; mt++) {
        int row = m0 + wm * 32 + mt * 16 + lr;
        #pragma unroll
        for (int nt = 0; nt < 8; nt++) {
            int col = n0 + wn * 64 + nt * 8 + (lane & 3) * 2;
            float v0 = acc[mt][nt][0], v1 = acc[mt][nt][1];
            float v2 = acc[mt][nt][2], v3 = acc[mt][nt][3];
            float h0 = __bfloat162float(__float2bfloat16(v0));
            float h1 = __bfloat162float(__float2bfloat16(v1));
            float h2 = __bfloat162float(__float2bfloat16(v2));
            float h3 = __bfloat162float(__float2bfloat16(v3));
            size_t o0 = (size_t)row * 1024 + col;
            size_t o1 = (size_t)(row + 8) * 1024 + col;
            *reinterpret_cast<uint32_t*>(Chi + o0) = packbf2(v0, v1);
            *reinterpret_cast<uint32_t*>(Chi + o1) = packbf2(v2, v3);
            *reinterpret_cast<uint32_t*>(Clo + o0) = packbf2(v0 - h0, v1 - h1);
            *reinterpret_cast<uint32_t*>(Clo + o1) = packbf2(v2 - h2, v3 - h3);
        }
    }
}

// ---------------------------------------------------------------------------
// Tensorized gate GEMM + fused LSTM + fused comb_{t+1}.
// v64 tile (R5 shape). W comes from prepacked global fragments (LDG.128),
// only G goes through smem -> 18.4KB smem, 2 CTAs/SM.
#define RKG 144
#define GS_PLANE (32*RKG)            // 4608
#define GATE_CHUNK (2*GS_PLANE)      // 9216
#define GATE_SMEM (2*GATE_CHUNK)     // 18432

__global__ __launch_bounds__(256, 2) void gate_lstm_mma(
    const float* __restrict__ bias, float* __restrict__ ysOut,
    const float* __restrict__ xnext)
{
    extern __shared__ char smem[];
    uint32_t sb = smem_to_u32(smem);
    const int tid = threadIdx.x, lane = tid & 31, wid = tid >> 5;
    const int wm = wid & 3, wn = wid >> 2;       // warp tile M64 x N32
    const int v0 = blockIdx.x * 64;
    const int b  = blockIdx.y;
    const int grp = lane >> 3, lr8 = lane & 7;

    const __nv_bfloat16* GHI[3] = {g_combhi, g_x1hi, g_x2hi};
    const __nv_bfloat16* GLO[3] = {g_comblo, g_x1lo, g_x2lo};

    float acc[4][4][4];
    #pragma unroll
    for (int mt = 0; mt < 4; mt++)
        #pragma unroll
        for (int nt = 0; nt < 4; nt++)
            #pragma unroll
            for (int q = 0; q < 4; q++) acc[mt][nt][q] = 0.f;

    auto load_chunk = [&](int ck, uint32_t base) {
        int plane = ck >> 1, coff = (ck & 1) * 32;
        int kl = tid >> 3, i8 = tid & 7;
        size_t gsrc = (((size_t)(b * 64 + coff + kl)) << 10) + v0 + i8 * 8;
        uint32_t gd = base + (uint32_t)(kl * RKG + i8 * 16);
        cpasync16(gd,            GHI[plane] + gsrc);
        cpasync16(gd + GS_PLANE, GLO[plane] + gsrc);
        CP_COMMIT();
    };

    load_chunk(0, sb);

    for (int ck = 0; ck < 6; ck++) {
        uint32_t base = sb + (ck & 1) * GATE_CHUNK;
        if (ck + 1 < 6) {
            load_chunk(ck + 1, sb + ((ck + 1) & 1) * GATE_CHUNK);
            CP_WAIT(1);
        } else {
            CP_WAIT(0);
        }
        __syncthreads();

        #pragma unroll
        for (int ks = 0; ks < 2; ks++) {
            int kk = ck * 2 + ks;
            // B fragments (G, trans ldmatrix) from smem
            uint32_t bh[4][2], bl[4][2];
            #pragma unroll
            for (int h = 0; h < 2; h++) {
                uint32_t a = base +
                    (uint32_t)((ks * 16 + (grp & 1) * 8 + lr8) * RKG) +
                    (uint32_t)(wn * 64 + h * 32 + (grp >> 1) * 16);
                uint32_t r[4];
                ldsm_x4_trans(r, a);
                bh[2 * h][0] = r[0]; bh[2 * h][1] = r[1];
                bh[2 * h + 1][0] = r[2]; bh[2 * h + 1][1] = r[3];
                ldsm_x4_trans(r, a + GS_PLANE);
                bl[2 * h][0] = r[0]; bl[2 * h][1] = r[1];
                bl[2 * h + 1][0] = r[2]; bl[2 * h + 1][1] = r[3];
            }
            // W fragments from global (L1/L2-hot; identical across CTAs)
            #pragma unroll
            for (int mt = 0; mt < 4; mt++) {
                int fidx = ((wm * 4 + mt) * 12 + kk) * 32 + lane;
                uint4 H = g_WfHi[fidx];
                uint4 L = g_WfLo[fidx];
                uint32_t ah[4] = {H.x, H.y, H.z, H.w};
                uint32_t al[4] = {L.x, L.y, L.z, L.w};
                #pragma unroll
                for (int nt = 0; nt < 4; nt++) {
                    mma16816(acc[mt][nt], ah, bh[nt]);
                    mma16816(acc[mt][nt], ah, bl[nt]);
                    mma16816(acc[mt][nt], al, bh[nt]);
                }
            }
        }
        __syncthreads();
    }

    // Fused LSTM epilogue + comb_{t+1} generation.
    const int r = lane >> 2;
    const int q2 = (lane & 3) * 2;
    #pragma unroll
    for (int s = 0; s < 2; s++) {
        int c = wm * 16 + r + 8 * s;
        float bi = bias[c];
        float bf = bias[64 + c];
        float bg = bias[128 + c];
        float bo = bias[192 + c];
        #pragma unroll
        for (int nt = 0; nt < 4; nt++) {
            int v = v0 + wn * 32 + nt * 8 + q2;
            size_t idx = (size_t)b * CVSZ + (size_t)c * VV + v;
            float2 cold = *reinterpret_cast<const float2*>(g_c + idx);
            float i0 = acc[0][nt][2 * s]     + bi;
            float i1 = acc[0][nt][2 * s + 1] + bi;
            float f0 = acc[1][nt][2 * s]     + bf;
            float f1 = acc[1][nt][2 * s + 1] + bf;
            float g0 = acc[2][nt][2 * s]     + bg;
            float g1 = acc[2][nt][2 * s + 1] + bg;
            float o0 = acc[3][nt][2 * s]     + bo;
            float o1 = acc[3][nt][2 * s + 1] + bo;
            float cy0 = sigf(f0) * cold.x + sigf(i0) * g0;
            float cy1 = sigf(f1) * cold.y + sigf(i1) * g1;
            float hy0 = sigf(o0) * tanh_fast(cy0);
            float hy1 = sigf(o1) * tanh_fast(cy1);
            *reinterpret_cast<float2*>(g_c + idx)   = make_float2(cy0, cy1);
            *reinterpret_cast<float2*>(ysOut + idx) = make_float2(hy0, hy1);
            if (xnext) {
                float2 xv = *reinterpret_cast<const float2*>(xnext + idx);
                float cb0 = xv.x + hy0, cb1 = xv.y + hy1;
                float hb0 = __bfloat162float(__float2bfloat16(cb0));
                float hb1 = __bfloat162float(__float2bfloat16(cb1));
                *reinterpret_cast<uint32_t*>(g_combhi + idx) = packbf2(cb0, cb1);
                *reinterpret_cast<uint32_t*>(g_comblo + idx) = packbf2(cb0 - hb0, cb1 - hb1);
            }
        }
    }
}

// ---------------------------------------------------------------------------
__global__ __launch_bounds__(256) void proj_out(const float* __restrict__ Wout,
                                                const float* __restrict__ bout,
                                                float* __restrict__ out) {
    __shared__ float sm[TT * CC * 8];
    int b  = blockIdx.y;
    int v0 = blockIdx.x * 8;
    for (int i = threadIdx.x; i < TT * CC * 8; i += 256) {
        int t = i / (CC * 8);
        int rem = i % (CC * 8);
        int c = rem >> 3, vv = rem & 7;
        sm[i] = g_ys[(size_t)t * PART + (size_t)b * CVSZ + (size_t)c * VV + v0 + vv];
    }
    __syncthreads();
    for (int p = threadIdx.x; p < COUT * 8; p += 256) {
        int o = p >> 3, vv = p & 7;
        float accp[TT];
        #pragma unroll
        for (int t = 0; t < TT; t++) accp[t] = 0.f;
        for (int c = 0; c < CC; c++) {
            float w = Wout[o * CC + c];
            #pragma unroll
            for (int t = 0; t < TT; t++) accp[t] += w * sm[t * (CC * 8) + c * 8 + vv];
        }
        float bo = bout[o];
        float* op = out + ((size_t)(b * COUT + o) * VV + v0 + vv) * TT;
        #pragma unroll
        for (int t = 0; t < TT; t++) op[t] = accp[t] + bo;
    }
}

// ---------------------------------------------------------------------------
extern "C" void kernel_launch(void* const* d_in, const int* in_sizes, int n_in,
                              void* d_out, int out_size) {
    const float* x      = (const float*)d_in[0];
    const float* Amat   = (const float*)d_in[1];
    const float* W_gout = (const float*)d_in[2];
    const float* b_gout = (const float*)d_in[3];
    const float* W_out  = (const float*)d_in[4];
    const float* b_out  = (const float*)d_in[5];
    float* out = (float*)d_out;

    float *xT, *ys;
    __nv_bfloat16 *chi, *clo, *x1hi, *x1lo, *x2hi, *x2lo;
    cudaGetSymbolAddress((void**)&xT, g_xT);
    cudaGetSymbolAddress((void**)&ys, g_ys);
    cudaGetSymbolAddress((void**)&chi,  g_combhi);
    cudaGetSymbolAddress((void**)&clo,  g_comblo);
    cudaGetSymbolAddress((void**)&x1hi, g_x1hi);
    cudaGetSymbolAddress((void**)&x1lo, g_x1lo);
    cudaGetSymbolAddress((void**)&x2hi, g_x2hi);
    cudaGetSymbolAddress((void**)&x2lo, g_x2lo);

    cudaFuncSetAttribute(hop_mma, cudaFuncAttributeMaxDynamicSharedMemorySize, HOP_SMEM);
    cudaFuncSetAttribute(gate_lstm_mma, cudaFuncAttributeMaxDynamicSharedMemorySize, GATE_SMEM);

    transpose_x<<<dim3(MROWS, VV / 32), 256>>>(x);
    zero_c<<<(MROWS * VV) / 256, 256>>>();
    bsplit<<<dim3(32, 32), 256>>>(Amat);
    wfrag<<<16 * 12, 32>>>(W_gout);
    comb_init<<<(MROWS * VV / 4) / 256, 256>>>(xT);   // comb_0 = x_0

    dim3 hopGrid(VV / 128, MROWS / 128);    // (8, 16) = 128 CTAs
    dim3 gateGrid(VV / 64, BB);             // (16, 32) = 512 CTAs, 2/SM

    for (int t = 0; t < TT; t++) {
        hop_mma<<<hopGrid, 256, HOP_SMEM>>>(chi, clo, x1hi, x1lo);    // x1 = comb @ A
        hop_mma<<<hopGrid, 256, HOP_SMEM>>>(x1hi, x1lo, x2hi, x2lo);  // x2 = x1 @ A
        const float* xnext = (t + 1 < TT) ? (xT + (size_t)(t + 1) * PART) : nullptr;
        gate_lstm_mma<<<gateGrid, 256, GATE_SMEM>>>(b_gout, ys + (size_t)t * PART, xnext);
    }

    proj_out<<<dim3(VV / 8, BB), 256>>>(W_out, b_out, out);
}